// round 1
// baseline (speedup 1.0000x reference)
#include <cuda_runtime.h>
#include <cstdint>

#define BB 64
#define NN 1024

// Output layout (flattened reference tuple, all float32):
//   [0]                     done
//   [1 .. 1+B*N)            new_mask
//   [65537 .. +B*N*N)       adj
//   [.. +B)                 future_actions
//   [.. +B)                 present_time_new
//   [.. +B)                 step_mask
#define OFF_DONE 0
#define OFF_NM   1
#define OFF_ADJ  (1 + BB*NN)
#define OFF_FA   (OFF_ADJ + (size_t)BB*NN*NN)
#define OFF_PT   (OFF_FA + BB)
#define OFF_STEP (OFF_PT + BB)

__device__ float g_fp[BB * NN];     // fpresent[b, i]
__device__ float g_dlast[NN];       // dist[:, N-1] contiguous

__global__ void k_init(float* out) {
    out[OFF_DONE] = 1.0f;  // done = true unless any new_mask[:, -1] > 0
}

__global__ void k_prep(const float* __restrict__ inputs,
                       const float* __restrict__ dist,
                       const float* __restrict__ mask,
                       const float* __restrict__ ptime,
                       const int*   __restrict__ pres,
                       const int*   __restrict__ fut,
                       float* out)
{
    int b = blockIdx.x;
    int j = threadIdx.x;

    int   pa = pres[b];
    float pt = ptime[b];

    // inputs is AoS: (b, j, {open, close, dur, ttime}); 16B aligned
    float4 in4 = *reinterpret_cast<const float4*>(inputs + ((size_t)(b * NN + j)) * 4);
    float op = in4.x, cl = in4.y, dur = in4.z;
    float T0 = inputs[3];                       // inputs[0,0,ARR] (global scalar for c2)

    float dlast  = dist[(size_t)j * NN + (NN - 1)];
    float arrive = dist[(size_t)pa * NN + j] + pt;
    float wait   = fmaxf(0.0f, op - arrive);
    float t      = arrive + wait;

    bool c1 = t <= cl;
    bool c2 = ((t + dur) + dlast) <= T0;

    float m = mask[b * NN + j];
    if (j == pa) m = 0.0f;
    float nm = (c1 && c2) ? m : 0.0f;

    float fpres = t + dur;                      // farrive + fwait + durat

    out[OFF_NM + b * NN + j] = nm;
    g_fp[b * NN + j] = fpres;
    if (b == 0) g_dlast[j] = dlast;

    if (j == NN - 1 && nm > 0.0f) out[OFF_DONE] = 0.0f;   // same-value writes, race-free

    int fb = fut[b];
    if (j == fb) out[OFF_PT + b] = fpres;       // present_time_new[b] == fpresent[b, fut]
    if (j == 0) {
        out[OFF_FA + b]   = (float)fb;
        out[OFF_STEP + b] = 1.0f;
    }
}

// adj kernel: block = (i-tile of R rows) x (batch-tile of BT batches).
// Scalar, warp-coalesced loads/stores (adj base is only 4B-aligned).
#define BT 4
#define RR 8

__global__ __launch_bounds__(256) void k_adj(const float* __restrict__ inputs,
                                             const float* __restrict__ dist,
                                             float* out)
{
    const int ITILES = NN / RR;                 // 128
    int itile = blockIdx.x % ITILES;
    int b0    = (blockIdx.x / ITILES) * BT;
    int i0    = itile * RR;
    int tid   = threadIdx.x;

    float dl[4];
#pragma unroll
    for (int q = 0; q < 4; q++) dl[q] = g_dlast[tid + 256 * q];

    const float* nm_base = out + OFF_NM;

    for (int bb = 0; bb < BT; bb++) {
        int b = b0 + bb;

        float4 in4[4];
        float  nm[4];
#pragma unroll
        for (int q = 0; q < 4; q++) {
            int j = tid + 256 * q;
            in4[q] = *reinterpret_cast<const float4*>(inputs + ((size_t)(b * NN + j)) * 4);
            nm[q]  = nm_base[b * NN + j];
        }
        float Tb = inputs[((size_t)b * NN) * 4 + 3];   // inputs[b,0,ARR]

#pragma unroll
        for (int r = 0; r < RR; r++) {
            int i = i0 + r;
            float fp = g_fp[b * NN + i];
            const float* drow = dist + (size_t)i * NN;
            float* orow = out + OFF_ADJ + ((size_t)(b * NN + i)) * NN;

#pragma unroll
            for (int q = 0; q < 4; q++) {
                int j = tid + 256 * q;
                float arr2 = drow[j] + fp;
                float w    = fmaxf(0.0f, in4[q].x - arr2);
                float s    = arr2 + w;
                bool a1 = s <= in4[q].y;
                bool a2 = ((s + in4[q].z) + dl[q]) <= Tb;
                float v = (a1 && a2) ? nm[q] : 0.0f;
                if (j == i) v = 1.0f;               // eye override
                orow[j] = v;
            }
        }
    }
}

extern "C" void kernel_launch(void* const* d_in, const int* in_sizes, int n_in,
                              void* d_out, int out_size)
{
    const float* inputs = (const float*)d_in[0];   // (B, N, 4) f32
    const float* dist   = (const float*)d_in[1];   // (N, N)   f32
    const float* mask   = (const float*)d_in[2];   // (B, N)   f32
    const float* ptime  = (const float*)d_in[3];   // (B, 1)   f32
    const int*   pres   = (const int*)d_in[4];     // (B,)     i32
    const int*   fut    = (const int*)d_in[5];     // (B,)     i32
    float* out = (float*)d_out;

    k_init<<<1, 1>>>(out);
    k_prep<<<BB, NN>>>(inputs, dist, mask, ptime, pres, fut, out);
    k_adj<<<(NN / RR) * (BB / BT), 256>>>(inputs, dist, out);
}